// round 1
// baseline (speedup 1.0000x reference)
#include <cuda_runtime.h>
#include <cstddef>

#define N_USERS 200000
#define N_ITEMS 100000
#define N_NODES 300000
#define DIM     64
#define N_EDGES 1200000

// Scratch accumulator for segment_sum (76.8 MB, zeroed each launch by a kernel).
__device__ float g_agg[(size_t)N_NODES * DIM];
// 1 if filt == eye(64), else 0. Recomputed every launch (deterministic).
__device__ int g_identity;

__device__ __forceinline__ float sigf(float x) {
    return 1.0f / (1.0f + __expf(-x));
}

// ---------------------------------------------------------------------------
// Zero the accumulator (float4 stores, 4.8M threads)
// ---------------------------------------------------------------------------
__global__ void zero_agg_kernel() {
    unsigned idx = blockIdx.x * blockDim.x + threadIdx.x;
    if (idx < (unsigned)(N_NODES * (DIM / 4))) {
        reinterpret_cast<float4*>(g_agg)[idx] = make_float4(0.f, 0.f, 0.f, 0.f);
    }
}

// ---------------------------------------------------------------------------
// Check whether filt is the identity matrix (single block)
// ---------------------------------------------------------------------------
__global__ void check_filt_kernel(const float* __restrict__ filt) {
    __shared__ int ok;
    if (threadIdx.x == 0) ok = 1;
    __syncthreads();
    for (int i = threadIdx.x; i < DIM * DIM; i += blockDim.x) {
        int r = i / DIM, c = i % DIM;
        float expect = (r == c) ? 1.0f : 0.0f;
        if (filt[i] != expect) atomicAnd(&ok, 0);
    }
    __syncthreads();
    if (threadIdx.x == 0) g_identity = ok;
}

// ---------------------------------------------------------------------------
// Edge scatter: agg[row] += val * emb[col]
// 16 threads per edge, one float4 (16B) per thread, vector L2 reduction.
// ---------------------------------------------------------------------------
__global__ void edge_kernel(const int*   __restrict__ rows,
                            const int*   __restrict__ cols,
                            const float* __restrict__ vals,
                            const float4* __restrict__ ue4,
                            const float4* __restrict__ ie4) {
    unsigned idx = blockIdx.x * blockDim.x + threadIdx.x;
    if (idx >= (unsigned)N_EDGES * 16u) return;
    unsigned e = idx >> 4;
    unsigned c = idx & 15u;

    int   col = __ldg(cols + e);
    int   row = __ldg(rows + e);
    float v   = __ldg(vals + e);

    float4 x = (col < N_USERS)
        ? __ldg(ue4 + (size_t)col * 16 + c)
        : __ldg(ie4 + (size_t)(col - N_USERS) * 16 + c);

    x.x *= v; x.y *= v; x.z *= v; x.w *= v;

    float4* dst = reinterpret_cast<float4*>(g_agg) + (size_t)row * 16 + c;
    asm volatile("red.global.add.v4.f32 [%0], {%1, %2, %3, %4};"
                 :: "l"(dst), "f"(x.x), "f"(x.y), "f"(x.z), "f"(x.w)
                 : "memory");
}

// ---------------------------------------------------------------------------
// Epilogue: out[n] = [ emb[n] (64) | sigmoid((2*emb[n]-agg[n]) @ filt) (64) ]
// 16 threads/node, float4 per thread. Fast path when filt == I.
// blockDim must be 256 (16 nodes per block) for the generic fallback path.
// ---------------------------------------------------------------------------
__global__ void out_kernel(const float4* __restrict__ ue4,
                           const float4* __restrict__ ie4,
                           const float*  __restrict__ filt,
                           float4*       __restrict__ out4) {
    unsigned idx = blockIdx.x * blockDim.x + threadIdx.x;
    unsigned n = idx >> 4;
    unsigned c = idx & 15u;
    bool active = (n < (unsigned)N_NODES);

    float4 e = make_float4(0.f, 0.f, 0.f, 0.f);
    float4 a = make_float4(0.f, 0.f, 0.f, 0.f);
    if (active) {
        e = (n < N_USERS) ? __ldg(ue4 + (size_t)n * 16 + c)
                          : __ldg(ie4 + (size_t)(n - N_USERS) * 16 + c);
        a = reinterpret_cast<const float4*>(g_agg)[(size_t)n * 16 + c];
        // first 64 columns: raw embedding
        out4[(size_t)n * 32 + c] = e;
    }

    float4 t;
    t.x = 2.0f * e.x - a.x;
    t.y = 2.0f * e.y - a.y;
    t.z = 2.0f * e.z - a.z;
    t.w = 2.0f * e.w - a.w;

    if (g_identity) {
        if (active) {
            float4 h;
            h.x = sigf(t.x); h.y = sigf(t.y); h.z = sigf(t.z); h.w = sigf(t.w);
            out4[(size_t)n * 32 + 16 + c] = h;
        }
    } else {
        // Generic fallback: t @ filt with t staged in shared memory.
        __shared__ float ts[16][DIM];
        unsigned ln = threadIdx.x >> 4;   // local node slot within block
        ts[ln][c * 4 + 0] = t.x;
        ts[ln][c * 4 + 1] = t.y;
        ts[ln][c * 4 + 2] = t.z;
        ts[ln][c * 4 + 3] = t.w;
        __syncthreads();
        if (active) {
            const float* trow = ts[ln];
            float4 h;
            float s[4] = {0.f, 0.f, 0.f, 0.f};
            #pragma unroll 8
            for (int k = 0; k < DIM; k++) {
                float tk = trow[k];
                const float* frow = filt + (size_t)k * DIM + c * 4;
                s[0] += tk * frow[0];
                s[1] += tk * frow[1];
                s[2] += tk * frow[2];
                s[3] += tk * frow[3];
            }
            h.x = sigf(s[0]); h.y = sigf(s[1]); h.z = sigf(s[2]); h.w = sigf(s[3]);
            out4[(size_t)n * 32 + 16 + c] = h;
        }
    }
}

// ---------------------------------------------------------------------------
// Launch
// ---------------------------------------------------------------------------
extern "C" void kernel_launch(void* const* d_in, const int* in_sizes, int n_in,
                              void* d_out, int out_size) {
    const int*   rows = (const int*)  d_in[0];
    const int*   cols = (const int*)  d_in[1];
    const float* vals = (const float*)d_in[2];
    const float* ue   = (const float*)d_in[3];
    const float* ie   = (const float*)d_in[4];
    const float* filt = (const float*)d_in[5];
    float*       out  = (float*)d_out;

    const unsigned zero_threads = N_NODES * (DIM / 4);           // 4.8M
    zero_agg_kernel<<<(zero_threads + 255) / 256, 256>>>();

    check_filt_kernel<<<1, 256>>>(filt);

    const unsigned edge_threads = (unsigned)N_EDGES * 16u;       // 19.2M
    edge_kernel<<<(edge_threads + 255) / 256, 256>>>(
        rows, cols, vals, (const float4*)ue, (const float4*)ie);

    const unsigned out_threads = (unsigned)N_NODES * 16u;        // 4.8M
    out_kernel<<<(out_threads + 255) / 256, 256>>>(
        (const float4*)ue, (const float4*)ie, filt, (float4*)out);
}